// round 4
// baseline (speedup 1.0000x reference)
#include <cuda_runtime.h>
#include <math.h>

#define DIMV 256
#define HEADSV 8
#define BSZ 8
#define NN 1024

typedef unsigned long long u64;

// ---- scratch (device globals: no allocations allowed) ----
__device__ float g_fp[BSZ * NN * DIMV * HEADSV];    // 64 MB  feat_proj [8192][2048]
__device__ float g_attn[BSZ * NN * DIMV * HEADSV];  // 64 MB  attn out  [8192][2048]
__device__ float g_qv[BSZ * HEADSV * NN];
__device__ float g_kv[BSZ * HEADSV * NN];
__device__ float g_Ae[BSZ * HEADSV * NN];
__device__ float g_Be[BSZ * HEADSV * NN];
__device__ float g_Ce[BSZ * HEADSV * NN];
__device__ float g_De[BSZ * HEADSV * NN];

// ---- packed f32x2 helpers (sm_103a) ----
__device__ __forceinline__ u64 pack2(float x, float y) {
    u64 r; asm("mov.b64 %0, {%1, %2};" : "=l"(r) : "f"(x), "f"(y)); return r;
}
__device__ __forceinline__ void unpack2(u64 v, float &x, float &y) {
    asm("mov.b64 {%0, %1}, %2;" : "=f"(x), "=f"(y) : "l"(v));
}
__device__ __forceinline__ void fma2(u64 &d, u64 a, u64 b) {
    asm("fma.rn.f32x2 %0, %1, %2, %0;" : "+l"(d) : "l"(a), "l"(b));
}

// ============================================================================
// Generic f32x2 tiled GEMM: C[M][ldn-window] = A[M][K] @ B[K][ldn] (+bias, +epi)
// Tile: BM x 256, K-tile 64, 256 threads, thread micro-tile (BM/8) x 8 cols
// (cols paired (c, c+128) inside the 256-col window for packed FMA).
// EPI 0: +bias.  EPI 1: +bias +resid, sigmoid.
// ============================================================================
template<int BM, int EPI>
__global__ __launch_bounds__(256, 2)
void gemm_kernel(const float* __restrict__ A, const float* __restrict__ B,
                 const float* __restrict__ bias, const float* __restrict__ resid,
                 float* __restrict__ C, int K, int ldn)
{
    constexpr int KT  = 64;
    constexpr int RPT = BM / 8;
    extern __shared__ char sm_raw[];
    u64* B2 = (u64*)sm_raw;        // [KT][128]  packed (c, c+128)
    u64* A2 = B2 + KT * 128;       // [BM][65]   packed (a, a) broadcast operand

    const int t   = threadIdx.x;
    const int txd = t & 31;
    const int tyi = t >> 5;
    const int m0  = blockIdx.x * BM;
    const int n0  = blockIdx.y * 256;

    u64 acc[RPT][4];
    #pragma unroll
    for (int r = 0; r < RPT; r++)
        #pragma unroll
        for (int d = 0; d < 4; d++) acc[r][d] = 0ULL;

    for (int k0 = 0; k0 < K; k0 += KT) {
        __syncthreads();
        // B tile: pack pairs (c, c+128)
        #pragma unroll
        for (int r = 0; r < (KT * 128) / 256; r++) {
            int idx = t + r * 256;
            int j = idx >> 7, c = idx & 127;
            const float* br = B + (size_t)(k0 + j) * ldn + n0;
            B2[j * 128 + c] = pack2(br[c], br[c + 128]);
        }
        // A tile: pre-pack {a,a} once (reused by 32 lanes)
        #pragma unroll
        for (int r = 0; r < (BM * KT) / 256; r++) {
            int idx = t + r * 256;
            int mi = idx >> 6, kk = idx & 63;
            float a = A[(size_t)(m0 + mi) * K + k0 + kk];
            A2[mi * 65 + kk] = pack2(a, a);
        }
        __syncthreads();
        #pragma unroll 16
        for (int kk = 0; kk < KT; kk++) {
            u64 vv[4];
            #pragma unroll
            for (int d = 0; d < 4; d++) vv[d] = B2[kk * 128 + txd + 32 * d];
            #pragma unroll
            for (int r = 0; r < RPT; r++) {
                u64 aa = A2[(tyi * RPT + r) * 65 + kk];
                #pragma unroll
                for (int d = 0; d < 4; d++) fma2(acc[r][d], aa, vv[d]);
            }
        }
    }

    #pragma unroll
    for (int r = 0; r < RPT; r++) {
        int m = m0 + tyi * RPT + r;
        #pragma unroll
        for (int d = 0; d < 4; d++) {
            int c = txd + 32 * d;
            float x0, x1; unpack2(acc[r][d], x0, x1);
            int c0 = n0 + c, c1 = n0 + c + 128;
            x0 += bias[c0]; x1 += bias[c1];
            if (EPI == 1) {
                x0 += resid[(size_t)m * ldn + c0];
                x1 += resid[(size_t)m * ldn + c1];
                x0 = 1.0f / (1.0f + expf(-x0));
                x1 = 1.0f / (1.0f + expf(-x1));
            }
            C[(size_t)m * ldn + c0] = x0;
            C[(size_t)m * ldn + c1] = x1;
        }
    }
}

// ============================================================================
// q/k scalar projections: one warp per (row, head).
// ============================================================================
__global__ void qk_kernel(const float* __restrict__ qw, const float* __restrict__ qb,
                          const float* __restrict__ kw, const float* __restrict__ kb)
{
    int r = blockIdx.x;               // 0..8191 = b*1024+n
    int t = threadIdx.x;
    int h = t >> 5, lane = t & 31;
    const float* row = g_fp + (size_t)r * 2048 + h * 256;
    float sq = 0.f, sk = 0.f;
    #pragma unroll
    for (int i = 0; i < 8; i++) {
        float f = row[lane + 32 * i];
        sq += f * qw[lane + 32 * i];
        sk += f * kw[lane + 32 * i];
    }
    #pragma unroll
    for (int o = 16; o > 0; o >>= 1) {
        sq += __shfl_down_sync(0xffffffffu, sq, o);
        sk += __shfl_down_sync(0xffffffffu, sk, o);
    }
    if (lane == 0) {
        int b = r >> 10, n = r & 1023;
        int bh = b * HEADSV + h;
        g_qv[bh * NN + n] = sq + qb[0];
        g_kv[bh * NN + n] = sk + kb[0];
    }
}

// ============================================================================
// Per-head: kmax = max_j k_j; then factored-exp vectors:
//   m_i = leaky(q_i + kmax)   (valid shift; softmax is shift-invariant)
//   A_i = e^{q_i - m_i}, C_i = e^{0.01 q_i - m_i}, B_j = e^{k_j}, D_j = e^{0.01 k_j}
// so exp(leaky(q_i+k_j) - m_i) = (q_i+k_j>=0) ? A_i*B_j : C_i*D_j.
// ============================================================================
__global__ void abcd_kernel()
{
    __shared__ float red[256];
    int bh = blockIdx.x, t = threadIdx.x;
    const float* kv = g_kv + bh * NN;
    float m = -1e30f;
    for (int n = t; n < NN; n += 256) m = fmaxf(m, kv[n]);
    red[t] = m; __syncthreads();
    for (int s = 128; s > 0; s >>= 1) {
        if (t < s) red[t] = fmaxf(red[t], red[t + s]);
        __syncthreads();
    }
    float kmax = red[0];
    const float* qv = g_qv + bh * NN;
    for (int n = t; n < NN; n += 256) {
        float q = qv[n], k = kv[n];
        float xm = q + kmax;
        float mi = (xm >= 0.f) ? xm : 0.01f * xm;
        g_Ae[bh * NN + n] = expf(q - mi);
        g_Ce[bh * NN + n] = expf(0.01f * q - mi);
        g_Be[bh * NN + n] = expf(k);
        g_De[bh * NN + n] = expf(0.01f * k);
    }
}

// ============================================================================
// Fused attention: per (b,h, 64-row i-tile), loop over 64-col j-tiles:
//   build P tile from adj + factored exps (masked entries exactly 0, matching
//   the fp32 reference where exp(~-1e7) underflows), accumulate l_i and
//   O += P @ V with packed f32x2 FMA, normalize by 1/l at the end.
// ============================================================================
__global__ __launch_bounds__(256, 2)
void attn_kernel(const float* __restrict__ adj)
{
    extern __shared__ char sm_raw[];
    u64* V2 = (u64*)sm_raw;            // [64][128] packed (d, d+128)
    u64* P2 = V2 + 64 * 128;           // [64][65]  packed {p,p}
    float* fs   = (float*)(P2 + 64 * 65);
    float* kv_t = fs;
    float* B_t  = fs + 64;
    float* D_t  = fs + 128;
    float* qv_i = fs + 192;
    float* A_i  = fs + 256;
    float* C_i  = fs + 320;
    float* l_sm = fs + 384;

    const int t   = threadIdx.x;
    const int txd = t & 31;
    const int tyi = t >> 5;
    const int bh  = blockIdx.x;
    const int b   = bh >> 3, h = bh & 7;
    const int i0  = blockIdx.y * 64;

    if (t < 64) {
        int gi = bh * NN + i0 + t;
        qv_i[t] = g_qv[gi]; A_i[t] = g_Ae[gi]; C_i[t] = g_Ce[gi];
    }

    u64 acc[8][4];
    #pragma unroll
    for (int r = 0; r < 8; r++)
        #pragma unroll
        for (int d = 0; d < 4; d++) acc[r][d] = 0ULL;
    float l_reg = 0.f;

    for (int jt = 0; jt < 16; jt++) {
        int j0 = jt * 64;
        __syncthreads();   // previous-tile readers done
        if (t < 64) {
            int gj = bh * NN + j0 + t;
            kv_t[t] = g_kv[gj]; B_t[t] = g_Be[gj]; D_t[t] = g_De[gj];
        }
        // V tile (pairs d, d+128) — g_fp row stride 2048
        #pragma unroll
        for (int r = 0; r < 32; r++) {
            int idx = t + r * 256;
            int j = idx >> 7, c = idx & 127;
            const float* row = g_fp + (size_t)(b * NN + j0 + j) * 2048 + h * 256;
            V2[j * 128 + c] = pack2(row[c], row[c + 128]);
        }
        __syncthreads();
        // P tile
        #pragma unroll
        for (int r = 0; r < 16; r++) {
            int idx = t + r * 256;
            int ti = idx >> 6, tj = idx & 63;
            float av = adj[(size_t)(b * NN + i0 + ti) * NN + j0 + tj];
            float x  = qv_i[ti] + kv_t[tj];
            float p  = (x >= 0.f) ? (A_i[ti] * B_t[tj]) : (C_i[ti] * D_t[tj]);
            p = (av != 0.f) ? p : 0.f;
            P2[ti * 65 + tj] = pack2(p, p);
        }
        __syncthreads();
        // l accumulation (threads 0..63 own one i-row each)
        if (t < 64) {
            const float* Pf = (const float*)P2;
            float s = 0.f;
            #pragma unroll
            for (int jj = 0; jj < 64; jj++) s += Pf[(t * 65 + jj) * 2];
            l_reg += s;
        }
        // O += P @ V
        #pragma unroll 8
        for (int jj = 0; jj < 64; jj++) {
            u64 vv[4];
            #pragma unroll
            for (int d = 0; d < 4; d++) vv[d] = V2[jj * 128 + txd + 32 * d];
            #pragma unroll
            for (int r = 0; r < 8; r++) {
                u64 pp = P2[(tyi * 8 + r) * 65 + jj];
                #pragma unroll
                for (int d = 0; d < 4; d++) fma2(acc[r][d], pp, vv[d]);
            }
        }
    }

    __syncthreads();
    if (t < 64) l_sm[t] = l_reg;
    __syncthreads();

    #pragma unroll
    for (int r = 0; r < 8; r++) {
        int il = tyi * 8 + r;
        float l = l_sm[il];
        float inv = (l > 0.f) ? 1.0f / l : 0.f;
        float* orow = g_attn + (size_t)(b * NN + i0 + il) * 2048 + h * 256;
        #pragma unroll
        for (int d = 0; d < 4; d++) {
            int c = txd + 32 * d;
            float x0, x1; unpack2(acc[r][d], x0, x1);
            orow[c]       = x0 * inv;
            orow[c + 128] = x1 * inv;
        }
    }
}

// ============================================================================
extern "C" void kernel_launch(void* const* d_in, const int* in_sizes, int n_in,
                              void* d_out, int out_size)
{
    const float* feats = (const float*)d_in[0];
    const float* adj   = (const float*)d_in[1];
    const float* fc_w  = (const float*)d_in[2];
    const float* fc_b  = (const float*)d_in[3];
    const float* q_w   = (const float*)d_in[4];
    const float* q_b   = (const float*)d_in[5];
    const float* k_w   = (const float*)d_in[6];
    const float* k_b   = (const float*)d_in[7];
    const float* fp_w  = (const float*)d_in[8];
    const float* fp_b  = (const float*)d_in[9];
    float* out = (float*)d_out;

    const int smem_g1 = 64 * 128 * 8 + 64 * 65 * 8;              // 98816
    const int smem_g3 = 64 * 128 * 8 + 32 * 65 * 8;              // 82176
    const int smem_at = 64 * 128 * 8 + 64 * 65 * 8 + 448 * 4;    // 100608

    cudaFuncSetAttribute(gemm_kernel<64, 0>, cudaFuncAttributeMaxDynamicSharedMemorySize, smem_g1);
    cudaFuncSetAttribute(gemm_kernel<32, 1>, cudaFuncAttributeMaxDynamicSharedMemorySize, smem_g3);
    cudaFuncSetAttribute(attn_kernel,        cudaFuncAttributeMaxDynamicSharedMemorySize, smem_at);

    float* fp_buf = nullptr;
    float* at_buf = nullptr;
    cudaGetSymbolAddress((void**)&fp_buf, g_fp);
    cudaGetSymbolAddress((void**)&at_buf, g_attn);

    // 1) feat_proj = feats @ fc_w + fc_b      [8192,256]@[256,2048]
    gemm_kernel<64, 0><<<dim3(8192 / 64, 2048 / 256), 256, smem_g1>>>(
        feats, fc_w, fc_b, nullptr, fp_buf, 256, 2048);

    // 2) q, k scalars per (b,h,n)
    qk_kernel<<<8192, 256>>>(q_w, q_b, k_w, k_b);

    // 3) per-head kmax + factored exp vectors
    abcd_kernel<<<64, 256>>>();

    // 4) fused masked-softmax attention + P@V
    attn_kernel<<<dim3(64, 16), 256, smem_at>>>(adj);

    // 5) out = sigmoid(attn_out @ fp_w + fp_b + feats)   [8192,2048]@[2048,256]
    gemm_kernel<32, 1><<<dim3(8192 / 32, 1), 256, smem_g3>>>(
        at_buf, fp_w, fp_b, feats, out, 2048, 256);
}

// round 6
// speedup vs baseline: 1.0729x; 1.0729x over previous
#include <cuda_runtime.h>
#include <math.h>

#define DIMV 256
#define HEADSV 8
#define BSZ 8
#define NN 1024

typedef unsigned long long u64;

// ---- scratch (device globals: no allocations allowed) ----
__device__ float g_fp[BSZ * NN * DIMV * HEADSV];    // 64 MB  feat_proj [8192][2048]
__device__ float g_attn[BSZ * NN * DIMV * HEADSV];  // 64 MB  attn out  [8192][2048]
__device__ float g_qv[BSZ * HEADSV * NN];
__device__ float g_kv[BSZ * HEADSV * NN];
__device__ float g_Ae[BSZ * HEADSV * NN];
__device__ float g_Be[BSZ * HEADSV * NN];
__device__ float g_Ce[BSZ * HEADSV * NN];
__device__ float g_De[BSZ * HEADSV * NN];
// sparse edge buckets: per (b*1024+i, jtile) up to 64 local-j bytes
__device__ unsigned char g_eidx[BSZ * NN * 16 * 64];   // 8 MB
__device__ int           g_jcnt[BSZ * NN * 16];

// ---- packed f32x2 helpers (sm_103a) ----
__device__ __forceinline__ u64 pack2(float x, float y) {
    u64 r; asm("mov.b64 %0, {%1, %2};" : "=l"(r) : "f"(x), "f"(y)); return r;
}
__device__ __forceinline__ void unpack2(u64 v, float &x, float &y) {
    asm("mov.b64 {%0, %1}, %2;" : "=f"(x), "=f"(y) : "l"(v));
}
__device__ __forceinline__ void fma2(u64 &d, u64 a, u64 b) {
    asm("fma.rn.f32x2 %0, %1, %2, %0;" : "+l"(d) : "l"(a), "l"(b));
}

// ============================================================================
// f32x2 tiled GEMM: C[M][256-window] = A[M][K] @ B[K][ldn] (+bias, +epi)
// A panel stored kk-major so 2 rows' broadcast operands come from 1 LDS.128.
// B tile packed as (c, c+128) u64 pairs; loaded as 2x LDS.128 per kk.
// Thread micro-tile: RPT rows x 8 cols (u64 set {2txd,2txd+1,64+2txd,65+2txd}).
// EPI 0: +bias.  EPI 1: +bias +resid, sigmoid.
// ============================================================================
template<int BM, int EPI>
__global__ __launch_bounds__(256, 2)
void gemm_kernel(const float* __restrict__ A, const float* __restrict__ B,
                 const float* __restrict__ bias, const float* __restrict__ resid,
                 float* __restrict__ C, int K, int ldn)
{
    constexpr int KT  = 64;
    constexpr int RPT = BM / 8;
    constexpr int LDA = BM + 2;
    extern __shared__ __align__(16) char sm_raw[];
    u64* B2 = (u64*)sm_raw;        // [KT][128]  packed (c, c+128)
    u64* A2 = B2 + KT * 128;       // [KT][LDA]  packed (a, a), kk-major

    const int t   = threadIdx.x;
    const int txd = t & 31;
    const int tyi = t >> 5;
    const int m0  = blockIdx.x * BM;
    const int n0  = blockIdx.y * 256;

    u64 acc[RPT][4];
    #pragma unroll
    for (int r = 0; r < RPT; r++)
        #pragma unroll
        for (int d = 0; d < 4; d++) acc[r][d] = 0ULL;

    for (int k0 = 0; k0 < K; k0 += KT) {
        __syncthreads();
        // B tile
        #pragma unroll
        for (int r = 0; r < (KT * 128) / 256; r++) {
            int idx = t + r * 256;
            int j = idx >> 7, c = idx & 127;
            const float* br = B + (size_t)(k0 + j) * ldn + n0;
            B2[j * 128 + c] = pack2(br[c], br[c + 128]);
        }
        // A tile, kk-major
        #pragma unroll
        for (int r = 0; r < (BM * KT) / 256; r++) {
            int idx = t + r * 256;
            int kk = idx & 63, mi = idx >> 6;
            float a = A[(size_t)(m0 + mi) * K + k0 + kk];
            A2[kk * LDA + mi] = pack2(a, a);
        }
        __syncthreads();
        #pragma unroll 8
        for (int kk = 0; kk < KT; kk++) {
            ulonglong2 v01 = *(const ulonglong2*)(B2 + kk * 128 + 2 * txd);
            ulonglong2 v23 = *(const ulonglong2*)(B2 + kk * 128 + 64 + 2 * txd);
            #pragma unroll
            for (int rr = 0; rr < RPT / 2; rr++) {
                ulonglong2 aa = *(const ulonglong2*)(A2 + kk * LDA + tyi * RPT + 2 * rr);
                fma2(acc[2*rr][0], aa.x, v01.x);
                fma2(acc[2*rr][1], aa.x, v01.y);
                fma2(acc[2*rr][2], aa.x, v23.x);
                fma2(acc[2*rr][3], aa.x, v23.y);
                fma2(acc[2*rr+1][0], aa.y, v01.x);
                fma2(acc[2*rr+1][1], aa.y, v01.y);
                fma2(acc[2*rr+1][2], aa.y, v23.x);
                fma2(acc[2*rr+1][3], aa.y, v23.y);
            }
        }
    }

    const int cA = n0 + 2 * txd;         // acc[r][0].lo , acc[r][1].lo at cA,cA+1
    const int cB = cA + 128;             // acc[r][0].hi , acc[r][1].hi
    const int cC = n0 + 64 + 2 * txd;    // acc[r][2].lo , acc[r][3].lo
    const int cD = cC + 128;             // acc[r][2].hi , acc[r][3].hi
    float bA0 = bias[cA], bA1 = bias[cA + 1];
    float bB0 = bias[cB], bB1 = bias[cB + 1];
    float bC0 = bias[cC], bC1 = bias[cC + 1];
    float bD0 = bias[cD], bD1 = bias[cD + 1];

    #pragma unroll
    for (int r = 0; r < RPT; r++) {
        int m = m0 + tyi * RPT + r;
        float a0, a1, b0, b1, c0, c1, d0, d1;
        unpack2(acc[r][0], a0, a1);
        unpack2(acc[r][1], b0, b1);
        unpack2(acc[r][2], c0, c1);
        unpack2(acc[r][3], d0, d1);
        float xA0 = a0 + bA0, xA1 = b0 + bA1;
        float xB0 = a1 + bB0, xB1 = b1 + bB1;
        float xC0 = c0 + bC0, xC1 = d0 + bC1;
        float xD0 = c1 + bD0, xD1 = d1 + bD1;
        float* crow = C + (size_t)m * ldn;
        if (EPI == 1) {
            const float* rrow = resid + (size_t)m * ldn;
            float2 rA = *(const float2*)(rrow + cA);
            float2 rB = *(const float2*)(rrow + cB);
            float2 rC = *(const float2*)(rrow + cC);
            float2 rD = *(const float2*)(rrow + cD);
            xA0 = 1.0f / (1.0f + expf(-(xA0 + rA.x)));
            xA1 = 1.0f / (1.0f + expf(-(xA1 + rA.y)));
            xB0 = 1.0f / (1.0f + expf(-(xB0 + rB.x)));
            xB1 = 1.0f / (1.0f + expf(-(xB1 + rB.y)));
            xC0 = 1.0f / (1.0f + expf(-(xC0 + rC.x)));
            xC1 = 1.0f / (1.0f + expf(-(xC1 + rC.y)));
            xD0 = 1.0f / (1.0f + expf(-(xD0 + rD.x)));
            xD1 = 1.0f / (1.0f + expf(-(xD1 + rD.y)));
        }
        *(float2*)(crow + cA) = make_float2(xA0, xA1);
        *(float2*)(crow + cB) = make_float2(xB0, xB1);
        *(float2*)(crow + cC) = make_float2(xC0, xC1);
        *(float2*)(crow + cD) = make_float2(xD0, xD1);
    }
}

// ============================================================================
// q/k scalar projections: one warp per (row, head).
// ============================================================================
__global__ void qk_kernel(const float* __restrict__ qw, const float* __restrict__ qb,
                          const float* __restrict__ kw, const float* __restrict__ kb)
{
    int r = blockIdx.x;               // 0..8191 = b*1024+n
    int t = threadIdx.x;
    int h = t >> 5, lane = t & 31;
    const float* row = g_fp + (size_t)r * 2048 + h * 256;
    float sq = 0.f, sk = 0.f;
    #pragma unroll
    for (int i = 0; i < 8; i++) {
        float f = row[lane + 32 * i];
        sq += f * qw[lane + 32 * i];
        sk += f * kw[lane + 32 * i];
    }
    #pragma unroll
    for (int o = 16; o > 0; o >>= 1) {
        sq += __shfl_down_sync(0xffffffffu, sq, o);
        sk += __shfl_down_sync(0xffffffffu, sk, o);
    }
    if (lane == 0) {
        int b = r >> 10, n = r & 1023;
        int bh = b * HEADSV + h;
        g_qv[bh * NN + n] = sq + qb[0];
        g_kv[bh * NN + n] = sk + kb[0];
    }
}

// ============================================================================
// Per-head factored-exp vectors (softmax shift-invariant; all products <= 1):
//   m_i = leaky(q_i + kmax); A=e^{q-m}, C=e^{.01q-m}, B=e^{k}, D=e^{.01k}
//   exp(leaky(q_i+k_j) - m_i) = (q_i+k_j>=0) ? A_i*B_j : C_i*D_j
// ============================================================================
__global__ void abcd_kernel()
{
    __shared__ float red[256];
    int bh = blockIdx.x, t = threadIdx.x;
    const float* kv = g_kv + bh * NN;
    float m = -1e30f;
    for (int n = t; n < NN; n += 256) m = fmaxf(m, kv[n]);
    red[t] = m; __syncthreads();
    for (int s = 128; s > 0; s >>= 1) {
        if (t < s) red[t] = fmaxf(red[t], red[t + s]);
        __syncthreads();
    }
    float kmax = red[0];
    const float* qv = g_qv + bh * NN;
    for (int n = t; n < NN; n += 256) {
        float q = qv[n], k = kv[n];
        float xm = q + kmax;
        float mi = (xm >= 0.f) ? xm : 0.01f * xm;
        g_Ae[bh * NN + n] = expf(q - mi);
        g_Ce[bh * NN + n] = expf(0.01f * q - mi);
        g_Be[bh * NN + n] = expf(k);
        g_De[bh * NN + n] = expf(0.01f * k);
    }
}

// ============================================================================
// Edge-bucket build: per (b,i) row, per 64-j tile, compact neighbor local-j's.
// One block per (b,i); warp w handles j-tile w via ballot compaction.
// Buckets are shared by all 8 heads.
// ============================================================================
__global__ void build_csr(const float* __restrict__ adj)
{
    int bi = blockIdx.x;                 // 0..8191
    int w = threadIdx.x >> 5;            // jtile 0..15
    int lane = threadIdx.x & 31;
    const float* row = adj + (size_t)bi * 1024 + w * 64;
    unsigned m1 = __ballot_sync(0xffffffffu, row[lane] != 0.f);
    unsigned m2 = __ballot_sync(0xffffffffu, row[32 + lane] != 0.f);
    int c1 = __popc(m1);
    unsigned lt = (1u << lane) - 1u;
    unsigned char* base = g_eidx + ((size_t)bi * 16 + w) * 64;
    if (m1 & (1u << lane)) base[__popc(m1 & lt)] = (unsigned char)lane;
    if (m2 & (1u << lane)) base[c1 + __popc(m2 & lt)] = (unsigned char)(32 + lane);
    if (lane == 0) g_jcnt[bi * 16 + w] = c1 + __popc(m2);
}

// ============================================================================
// Sparse attention: CTA = (bh, 64-row i-tile), warp owns 8 rows (full 256 d).
// Per 64-col j-tile: stage V tile (packed (d,d+128) u64) + per-j (k,B,D),
// then gather only actual neighbors via edge buckets:
//   p = (q_i+k_j>=0) ? A_i*B_j : C_i*D_j  (masked entries contribute exactly 0,
//   matching the fp32 reference where exp(~-1e7) underflows to 0);
//   l_i += p;  O_i += p * V_j  (4x fma.f32x2 per edge).
// Normalize by 1/l at the end.
// ============================================================================
__global__ __launch_bounds__(256, 2)
void attn_kernel()
{
    extern __shared__ __align__(16) char sm_raw[];
    u64* V2 = (u64*)sm_raw;                 // [64][128] packed (d, d+128)
    float4* kbd = (float4*)(V2 + 64 * 128); // [64] (kv, B, D, 0)

    const int t   = threadIdx.x;
    const int txd = t & 31;
    const int tyi = t >> 5;
    const int bh  = blockIdx.x;
    const int b   = bh >> 3, h = bh & 7;
    const int i0  = blockIdx.y * 64;

    float qv[8], Ae[8], Ce[8], lr[8];
    #pragma unroll
    for (int r = 0; r < 8; r++) {
        int gi = bh * NN + i0 + tyi * 8 + r;
        qv[r] = g_qv[gi]; Ae[r] = g_Ae[gi]; Ce[r] = g_Ce[gi]; lr[r] = 0.f;
    }

    u64 acc[8][4];
    #pragma unroll
    for (int r = 0; r < 8; r++)
        #pragma unroll
        for (int d = 0; d < 4; d++) acc[r][d] = 0ULL;

    for (int jt = 0; jt < 16; jt++) {
        int j0 = jt * 64;
        __syncthreads();   // previous-tile readers done
        #pragma unroll
        for (int rr = 0; rr < 32; rr++) {
            int idx = t + rr * 256;
            int j = idx >> 7, c = idx & 127;
            const float* vrow = g_fp + (size_t)(b * NN + j0 + j) * 2048 + h * 256;
            V2[j * 128 + c] = pack2(vrow[c], vrow[c + 128]);
        }
        if (t < 64) {
            int gj = bh * NN + j0 + t;
            kbd[t] = make_float4(g_kv[gj], g_Be[gj], g_De[gj], 0.f);
        }
        __syncthreads();

        #pragma unroll
        for (int r = 0; r < 8; r++) {
            int bk = (b * NN + i0 + tyi * 8 + r) * 16 + jt;
            int cnt = g_jcnt[bk];
            const unsigned char* eb = g_eidx + (size_t)bk * 64;
            for (int e0 = 0; e0 < cnt; e0 += 4) {
                unsigned chunk = *(const unsigned*)(eb + e0);
                #pragma unroll
                for (int s = 0; s < 4; s++) {
                    if (e0 + s < cnt) {
                        int jl = (chunk >> (8 * s)) & 255;
                        float4 kb = kbd[jl];
                        float x = qv[r] + kb.x;
                        float p = (x >= 0.f) ? Ae[r] * kb.y : Ce[r] * kb.z;
                        lr[r] += p;
                        u64 pp = pack2(p, p);
                        ulonglong2 v01 = *(const ulonglong2*)(V2 + jl * 128 + 2 * txd);
                        ulonglong2 v23 = *(const ulonglong2*)(V2 + jl * 128 + 64 + 2 * txd);
                        fma2(acc[r][0], pp, v01.x);
                        fma2(acc[r][1], pp, v01.y);
                        fma2(acc[r][2], pp, v23.x);
                        fma2(acc[r][3], pp, v23.y);
                    }
                }
            }
        }
    }

    #pragma unroll
    for (int r = 0; r < 8; r++) {
        float l = lr[r];
        float inv = (l > 0.f) ? 1.0f / l : 0.f;
        float* orow = g_attn + (size_t)(b * NN + i0 + tyi * 8 + r) * 2048 + h * 256;
        float a0, a1, b0, b1, c0, c1, d0, d1;
        unpack2(acc[r][0], a0, a1);   // cols (2txd,       2txd+128)
        unpack2(acc[r][1], b0, b1);   // cols (2txd+1,     2txd+129)
        unpack2(acc[r][2], c0, c1);   // cols (64+2txd,    192+2txd)
        unpack2(acc[r][3], d0, d1);   // cols (65+2txd,    193+2txd)
        *(float2*)(orow + 2 * txd)       = make_float2(a0 * inv, b0 * inv);
        *(float2*)(orow + 128 + 2 * txd) = make_float2(a1 * inv, b1 * inv);
        *(float2*)(orow + 64 + 2 * txd)  = make_float2(c0 * inv, d0 * inv);
        *(float2*)(orow + 192 + 2 * txd) = make_float2(c1 * inv, d1 * inv);
    }
}

// ============================================================================
extern "C" void kernel_launch(void* const* d_in, const int* in_sizes, int n_in,
                              void* d_out, int out_size)
{
    const float* feats = (const float*)d_in[0];
    const float* adj   = (const float*)d_in[1];
    const float* fc_w  = (const float*)d_in[2];
    const float* fc_b  = (const float*)d_in[3];
    const float* q_w   = (const float*)d_in[4];
    const float* q_b   = (const float*)d_in[5];
    const float* k_w   = (const float*)d_in[6];
    const float* k_b   = (const float*)d_in[7];
    const float* fp_w  = (const float*)d_in[8];
    const float* fp_b  = (const float*)d_in[9];
    float* out = (float*)d_out;

    const int smem_g1 = (64 * 128 + 64 * 66) * 8;   // 99328
    const int smem_g3 = (64 * 128 + 64 * 34) * 8;   // 82944
    const int smem_at = 64 * 128 * 8 + 64 * 16;     // 66560

    cudaFuncSetAttribute(gemm_kernel<64, 0>, cudaFuncAttributeMaxDynamicSharedMemorySize, smem_g1);
    cudaFuncSetAttribute(gemm_kernel<32, 1>, cudaFuncAttributeMaxDynamicSharedMemorySize, smem_g3);
    cudaFuncSetAttribute(attn_kernel,        cudaFuncAttributeMaxDynamicSharedMemorySize, smem_at);

    float* fp_buf = nullptr;
    float* at_buf = nullptr;
    cudaGetSymbolAddress((void**)&fp_buf, g_fp);
    cudaGetSymbolAddress((void**)&at_buf, g_attn);

    // 0) edge buckets from adjacency (shared across heads)
    build_csr<<<8192, 512>>>(adj);

    // 1) feat_proj = feats @ fc_w + fc_b      [8192,256]@[256,2048]
    gemm_kernel<64, 0><<<dim3(8192 / 64, 2048 / 256), 256, smem_g1>>>(
        feats, fc_w, fc_b, nullptr, fp_buf, 256, 2048);

    // 2) q, k scalars per (b,h,n)
    qk_kernel<<<8192, 256>>>(q_w, q_b, k_w, k_b);

    // 3) per-head kmax + factored exp vectors
    abcd_kernel<<<64, 256>>>();

    // 4) sparse masked-softmax attention (gather over edges only)
    attn_kernel<<<dim3(64, 16), 256, smem_at>>>();

    // 5) out = sigmoid(attn_out @ fp_w + fp_b + feats)   [8192,2048]@[2048,256]
    gemm_kernel<32, 1><<<dim3(8192 / 32, 1), 256, smem_g3>>>(
        at_buf, fp_w, fp_b, feats, out, 2048, 256);
}